// round 15
// baseline (speedup 1.0000x reference)
#include <cuda_runtime.h>
#include <cuda_bf16.h>
#include <mma.h>

using namespace nvcuda;

#define NN 50000
#define DH 128
#define EMAX 600000

__device__ __align__(16) float g_h[(size_t)NN * DH];   // h = A @ W
__device__ __align__(16) float g_b[(size_t)NN * DH];   // layer-1 activation
__device__ __align__(16) float g_deg[NN];
__device__ __align__(16) float g_dinv[NN];
__device__ __align__(16) int   g_cnt[NN];
__device__ __align__(16) int   g_rowstart[NN + 1];
__device__ __align__(16) int   g_fill[NN];
__device__ __align__(16) int   g_csr_src[EMAX];
__device__ __align__(16) float g_csr_norm[EMAX];
__device__ __align__(16) __nv_bfloat16 g_ahi[(size_t)NN * DH];
__device__ __align__(16) __nv_bfloat16 g_alo[(size_t)NN * DH];
__device__ __align__(16) __nv_bfloat16 g_whi[2 * DH * DH];   // W1 then W2
__device__ __align__(16) __nv_bfloat16 g_wlo[2 * DH * DH];
__device__ int g_is64;

// ---------------- probe + zero (fused, one launch) ----------------

__global__ void probe_zero_kernel(const int* __restrict__ ei32, int E, int n) {
    int i = blockIdx.x * blockDim.x + threadIdx.x;
    if (i < n) { g_deg[i] = 0.0f; g_cnt[i] = 0; }
    if (blockIdx.x == 0) {
        __shared__ int any_nonzero;
        if (threadIdx.x == 0) any_nonzero = 0;
        __syncthreads();
        for (int j = threadIdx.x; j < 1024; j += blockDim.x) {
            int idx = 2 * j + 1;
            if (idx < 2 * E && ei32[idx] != 0) atomicOr(&any_nonzero, 1);
        }
        __syncthreads();
        if (threadIdx.x == 0) g_is64 = (any_nonzero == 0) ? 1 : 0;
    }
}

__device__ __forceinline__ int load_edge_idx(const void* ei, size_t pos) {
    if (g_is64) return (int)((const long long*)ei)[pos];
    return ((const int*)ei)[pos];
}

__global__ void deg_kernel(const void* __restrict__ ei, const float* __restrict__ ew,
                           int E, int n) {
    int e = blockIdx.x * blockDim.x + threadIdx.x;
    if (e < E) {
        int d = load_edge_idx(ei, (size_t)E + e);
        if ((unsigned)d < (unsigned)n) {
            atomicAdd(&g_deg[d], ew[e]);
            atomicAdd(&g_cnt[d], 1);
        }
    }
}

// scan over g_cnt -> g_rowstart/g_fill, plus dinv (fused; single block)
__global__ __launch_bounds__(1024) void scan_dinv_kernel(int n) {
    __shared__ int partial[1024];
    int t = threadIdx.x;
    for (int i = t; i < n; i += 1024)
        g_dinv[i] = rsqrtf(g_deg[i] + 1.0f);
    int ch = (n + 1023) / 1024;
    int start = t * ch;
    int sum = 0;
    for (int i = 0; i < ch; i++) {
        int idx = start + i;
        if (idx < n) sum += g_cnt[idx];
    }
    partial[t] = sum;
    __syncthreads();
    for (int off = 1; off < 1024; off <<= 1) {
        int v = (t >= off) ? partial[t - off] : 0;
        __syncthreads();
        partial[t] += v;
        __syncthreads();
    }
    int run = (t > 0) ? partial[t - 1] : 0;
    for (int i = 0; i < ch; i++) {
        int idx = start + i;
        if (idx < n) {
            g_rowstart[idx] = run;
            g_fill[idx] = run;
            run += g_cnt[idx];
        }
    }
    if (t == 1023) g_rowstart[n] = partial[1023];
}

__global__ void build_csr_kernel(const void* __restrict__ ei, const float* __restrict__ ew,
                                 int E, int n) {
    int e = blockIdx.x * blockDim.x + threadIdx.x;
    if (e < E) {
        int s = load_edge_idx(ei, e);
        int d = load_edge_idx(ei, (size_t)E + e);
        if ((unsigned)s < (unsigned)n && (unsigned)d < (unsigned)n) {
            int pos = atomicAdd(&g_fill[d], 1);
            g_csr_src[pos] = s;
            g_csr_norm[pos] = g_dinv[s] * ew[e] * g_dinv[d];
        }
    }
}

// ---------------- bf16 hi/lo split conversions ----------------

__device__ __forceinline__ void bf16_split(float x, __nv_bfloat16& hi, __nv_bfloat16& lo) {
    hi = __float2bfloat16(x);
    lo = __float2bfloat16(x - __bfloat162float(hi));
}

// both weight matrices at once: 2*128*128 elements
__global__ void conv_w_kernel(const float* __restrict__ W1, const float* __restrict__ W2) {
    int i = blockIdx.x * blockDim.x + threadIdx.x;
    if (i >= 2 * DH * DH) return;
    float x = (i < DH * DH) ? W1[i] : W2[i - DH * DH];
    bf16_split(x, g_whi[i], g_wlo[i]);
}

// A (fp32, from x or g_b) -> g_ahi/g_alo
__global__ void conv_a_kernel(const float* __restrict__ A_ext, int total, int from_gb) {
    const float* A = from_gb ? (const float*)g_b : A_ext;
    int i = blockIdx.x * blockDim.x + threadIdx.x;
    if (i >= total) return;
    bf16_split(A[i], g_ahi[i], g_alo[i]);
}

// ---------------- GEMM: g_h[n,128] = A[n,128] @ W[128,128], 3xBF16 wmma ------
// 256 threads (8 warps), 128 rows/block, warp = 16x128 stripe.
// W hi/lo staged in 64KB dynamic smem; A hi/lo read from global (L2).

__global__ __launch_bounds__(256) void gemm_bf16_kernel(int n, int w_off) {
    extern __shared__ __nv_bfloat16 smem[];
    __nv_bfloat16* Whi = smem;                 // 128*128
    __nv_bfloat16* Wlo = smem + DH * DH;       // 128*128

    int t = threadIdx.x;
    // stage W hi/lo: 2*16384 bf16 = 64KB -> 4096 float4 / 256 threads = 16 each
#pragma unroll
    for (int i = 0; i < 8; i++) {
        int idx = t + i * 256;   // float4 slots 0..2047 per array
        ((float4*)Whi)[idx] = ((const float4*)(g_whi + w_off))[idx];
        ((float4*)Wlo)[idx] = ((const float4*)(g_wlo + w_off))[idx];
    }
    __syncthreads();

    int warp = t >> 5;
    int row0 = blockIdx.x * 128 + warp * 16;   // n % 16 == 0
    if (row0 >= n) return;

    wmma::fragment<wmma::accumulator, 16, 16, 16, float> acc[8];
#pragma unroll
    for (int i = 0; i < 8; i++) wmma::fill_fragment(acc[i], 0.0f);

    wmma::fragment<wmma::matrix_a, 16, 16, 16, __nv_bfloat16, wmma::row_major> ahi, alo;
    wmma::fragment<wmma::matrix_b, 16, 16, 16, __nv_bfloat16, wmma::row_major> bhi, blo;

#pragma unroll
    for (int k = 0; k < DH; k += 16) {
        wmma::load_matrix_sync(ahi, g_ahi + (size_t)row0 * DH + k, DH);
        wmma::load_matrix_sync(alo, g_alo + (size_t)row0 * DH + k, DH);
#pragma unroll
        for (int nt = 0; nt < 8; nt++) {
            wmma::load_matrix_sync(bhi, Whi + k * DH + nt * 16, DH);
            wmma::load_matrix_sync(blo, Wlo + k * DH + nt * 16, DH);
            wmma::mma_sync(acc[nt], ahi, bhi, acc[nt]);
            wmma::mma_sync(acc[nt], alo, bhi, acc[nt]);
            wmma::mma_sync(acc[nt], ahi, blo, acc[nt]);
        }
    }

#pragma unroll
    for (int nt = 0; nt < 8; nt++)
        wmma::store_matrix_sync(g_h + (size_t)row0 * DH + nt * 16, acc[nt],
                                DH, wmma::mem_row_major);
}

// ---------------- aggregate: warp per dst node, register accumulation ----------

__global__ __launch_bounds__(256) void agg_kernel(
    const float* __restrict__ bias, float* __restrict__ out_ext,
    int n, int to_gb, int do_relu)
{
    float* out = to_gb ? (float*)g_b : out_ext;
    int warp = (blockIdx.x * blockDim.x + threadIdx.x) >> 5;
    int lane = threadIdx.x & 31;
    if (warp >= n) return;

    float di = g_dinv[warp];
    float sl = di * di;
    float4 hv = *((const float4*)(g_h + (size_t)warp * 128) + lane);
    float4 bv = *((const float4*)bias + lane);
    float4 acc;
    acc.x = hv.x * sl + bv.x;
    acc.y = hv.y * sl + bv.y;
    acc.z = hv.z * sl + bv.z;
    acc.w = hv.w * sl + bv.w;

    int p  = g_rowstart[warp];
    int p1 = g_rowstart[warp + 1];

    for (; p + 3 < p1; p += 4) {
        int   s0 = g_csr_src[p],     s1 = g_csr_src[p + 1];
        int   s2 = g_csr_src[p + 2], s3 = g_csr_src[p + 3];
        float n0 = g_csr_norm[p],     n1 = g_csr_norm[p + 1];
        float n2 = g_csr_norm[p + 2], n3 = g_csr_norm[p + 3];
        float4 v0 = *((const float4*)(g_h + (size_t)s0 * 128) + lane);
        float4 v1 = *((const float4*)(g_h + (size_t)s1 * 128) + lane);
        float4 v2 = *((const float4*)(g_h + (size_t)s2 * 128) + lane);
        float4 v3 = *((const float4*)(g_h + (size_t)s3 * 128) + lane);
        acc.x += n0 * v0.x + n1 * v1.x + n2 * v2.x + n3 * v3.x;
        acc.y += n0 * v0.y + n1 * v1.y + n2 * v2.y + n3 * v3.y;
        acc.z += n0 * v0.z + n1 * v1.z + n2 * v2.z + n3 * v3.z;
        acc.w += n0 * v0.w + n1 * v1.w + n2 * v2.w + n3 * v3.w;
    }
    for (; p < p1; p++) {
        int   sa = g_csr_src[p];
        float na = g_csr_norm[p];
        float4 va = *((const float4*)(g_h + (size_t)sa * 128) + lane);
        acc.x += na * va.x;
        acc.y += na * va.y;
        acc.z += na * va.z;
        acc.w += na * va.w;
    }

    if (do_relu) {
        acc.x = fmaxf(acc.x, 0.f);
        acc.y = fmaxf(acc.y, 0.f);
        acc.z = fmaxf(acc.z, 0.f);
        acc.w = fmaxf(acc.w, 0.f);
    }
    *((float4*)(out + (size_t)warp * 128) + lane) = acc;
}

// ---------------- launch ----------------

extern "C" void kernel_launch(void* const* d_in, const int* in_sizes, int n_in,
                              void* d_out, int out_size) {
    const float* x  = (const float*)d_in[0];
    const void*  ei = d_in[1];
    const float* ew = (const float*)d_in[2];
    const float* W1 = (const float*)d_in[3];
    const float* b1 = (const float*)d_in[4];
    const float* W2 = (const float*)d_in[5];
    const float* b2 = (const float*)d_in[6];
    float*       out = (float*)d_out;

    int n = in_sizes[0] / 128;   // 50000
    int E = in_sizes[2];         // 600000

    const int B = 256;
    const int SMEM = 2 * DH * DH * sizeof(__nv_bfloat16);   // 64KB

    static int attr_done = 0;
    if (!attr_done) {
        cudaFuncSetAttribute(gemm_bf16_kernel,
                             cudaFuncAttributeMaxDynamicSharedMemorySize, SMEM);
        attr_done = 1;
    }

    int total = n * DH;

    probe_zero_kernel<<<(n + B - 1) / B, B>>>((const int*)ei, E, n);
    deg_kernel<<<(E + B - 1) / B, B>>>(ei, ew, E, n);
    scan_dinv_kernel<<<1, 1024>>>(n);
    build_csr_kernel<<<(E + B - 1) / B, B>>>(ei, ew, E, n);
    conv_w_kernel<<<(2 * DH * DH + B - 1) / B, B>>>(W1, W2);

    int gemm_blocks = (n + 127) / 128;
    int conv_blocks = (total + B - 1) / B;
    int agg_blocks  = (n * 32 + B - 1) / B;

    // layer 1: h = x@W1 ; g_b = relu(agg(h) + b1)
    conv_a_kernel<<<conv_blocks, B>>>(x, total, 0);
    gemm_bf16_kernel<<<gemm_blocks, 256, SMEM>>>(n, 0);
    agg_kernel<<<agg_blocks, B>>>(b1, out, n, 1, 1);

    // layer 2: h = g_b@W2 ; out = agg(h) + b2
    conv_a_kernel<<<conv_blocks, B>>>(x, total, 1);
    gemm_bf16_kernel<<<gemm_blocks, 256, SMEM>>>(n, DH * DH);
    agg_kernel<<<agg_blocks, B>>>(b2, out, n, 0, 0);
}

// round 16
// speedup vs baseline: 1.3102x; 1.3102x over previous
#include <cuda_runtime.h>

#define NN 50000
#define DH 128
#define EMAX 600000

__device__ __align__(16) float g_h[(size_t)NN * DH];   // h = A @ W
__device__ __align__(16) float g_b[(size_t)NN * DH];   // layer-1 activation
__device__ __align__(16) float g_deg[NN];
__device__ __align__(16) float g_dinv[NN];
__device__ __align__(16) int   g_cnt[NN];
__device__ __align__(16) int   g_rowstart[NN + 1];
__device__ __align__(16) int   g_fill[NN];
__device__ __align__(16) int   g_csr_src[EMAX];
__device__ __align__(16) float g_csr_norm[EMAX];
__device__ int g_is64;

// ---------------- probe + zero (fused) ----------------

__global__ void probe_zero_kernel(const int* __restrict__ ei32, int E, int n) {
    int i = blockIdx.x * blockDim.x + threadIdx.x;
    if (i < n) { g_deg[i] = 0.0f; g_cnt[i] = 0; }
    if (blockIdx.x == 0) {
        __shared__ int any_nonzero;
        if (threadIdx.x == 0) any_nonzero = 0;
        __syncthreads();
        for (int j = threadIdx.x; j < 1024; j += blockDim.x) {
            int idx = 2 * j + 1;
            if (idx < 2 * E && ei32[idx] != 0) atomicOr(&any_nonzero, 1);
        }
        __syncthreads();
        if (threadIdx.x == 0) g_is64 = (any_nonzero == 0) ? 1 : 0;
    }
}

__device__ __forceinline__ int load_edge_idx(const void* ei, size_t pos) {
    if (g_is64) return (int)((const long long*)ei)[pos];
    return ((const int*)ei)[pos];
}

__global__ void deg_kernel(const void* __restrict__ ei, const float* __restrict__ ew,
                           int E, int n) {
    int e = blockIdx.x * blockDim.x + threadIdx.x;
    if (e < E) {
        int d = load_edge_idx(ei, (size_t)E + e);
        if ((unsigned)d < (unsigned)n) {
            atomicAdd(&g_deg[d], ew[e]);
            atomicAdd(&g_cnt[d], 1);
        }
    }
}

// dinv + exclusive scan over g_cnt (fused; single 1024-thread block)
__global__ __launch_bounds__(1024) void scan_dinv_kernel(int n) {
    __shared__ int partial[1024];
    int t = threadIdx.x;
    for (int i = t; i < n; i += 1024)
        g_dinv[i] = rsqrtf(g_deg[i] + 1.0f);
    int ch = (n + 1023) / 1024;
    int start = t * ch;
    int sum = 0;
    for (int i = 0; i < ch; i++) {
        int idx = start + i;
        if (idx < n) sum += g_cnt[idx];
    }
    partial[t] = sum;
    __syncthreads();
    for (int off = 1; off < 1024; off <<= 1) {
        int v = (t >= off) ? partial[t - off] : 0;
        __syncthreads();
        partial[t] += v;
        __syncthreads();
    }
    int run = (t > 0) ? partial[t - 1] : 0;
    for (int i = 0; i < ch; i++) {
        int idx = start + i;
        if (idx < n) {
            g_rowstart[idx] = run;
            g_fill[idx] = run;
            run += g_cnt[idx];
        }
    }
    if (t == 1023) g_rowstart[n] = partial[1023];
}

__global__ void build_csr_kernel(const void* __restrict__ ei, const float* __restrict__ ew,
                                 int E, int n) {
    int e = blockIdx.x * blockDim.x + threadIdx.x;
    if (e < E) {
        int s = load_edge_idx(ei, e);
        int d = load_edge_idx(ei, (size_t)E + e);
        if ((unsigned)s < (unsigned)n && (unsigned)d < (unsigned)n) {
            int pos = atomicAdd(&g_fill[d], 1);
            g_csr_src[pos] = s;
            g_csr_norm[pos] = g_dinv[s] * ew[e] * g_dinv[d];
        }
    }
}

// ---------------- GEMM: g_h[n,128] = A[n,128] @ W[128,128] ------------------
// FFMA2 (packed f32x2) inner loop: 8 fma.rn.f32x2 per kk instead of 16 FFMA.
// 512 threads/block, 64 rows/block, thread tile 4 rows x 4 cols (2 f32x2 pairs).

__global__ __launch_bounds__(512) void gemm128_kernel(
    const float* __restrict__ A_ext, const float* __restrict__ W,
    int n, int from_gb)
{
    __shared__ float As[64][32];
    __shared__ __align__(16) float Ws[32][128];

    const float* A = from_gb ? (const float*)g_b : A_ext;

    int t = threadIdx.x;
    int row0 = blockIdx.x * 64;
    int tx = t & 31;
    int ty = t >> 5;

    unsigned long long acc[4][2];
#pragma unroll
    for (int i = 0; i < 4; i++) { acc[i][0] = 0ULL; acc[i][1] = 0ULL; }

    for (int k0 = 0; k0 < 128; k0 += 32) {
        {
            int r  = t >> 3;
            int cg = t & 7;
            int grow = row0 + r;
            float4 v = make_float4(0.f, 0.f, 0.f, 0.f);
            if (grow < n)
                v = *(const float4*)(A + (size_t)grow * 128 + k0 + cg * 4);
            *(float4*)(&As[r][cg * 4]) = v;
        }
#pragma unroll
        for (int i = 0; i < 2; i++) {
            int idx = t + i * 512;
            int kk = idx >> 5;
            int cg = idx & 31;
            *(float4*)(&Ws[kk][cg * 4]) =
                *(const float4*)(W + (size_t)(k0 + kk) * 128 + cg * 4);
        }
        __syncthreads();

#pragma unroll
        for (int kk = 0; kk < 32; kk++) {
            // two packed column pairs (w0,w1) (w2,w3): 16B-aligned smem read
            ulonglong2 wp = *(const ulonglong2*)(&Ws[kk][tx * 4]);
#pragma unroll
            for (int i = 0; i < 4; i++) {
                float a = As[ty * 4 + i][kk];   // warp-uniform broadcast
                unsigned long long ap;
                asm("mov.b64 %0, {%1, %1};" : "=l"(ap) : "r"(__float_as_uint(a)));
                asm("fma.rn.f32x2 %0, %1, %2, %0;" : "+l"(acc[i][0]) : "l"(ap), "l"(wp.x));
                asm("fma.rn.f32x2 %0, %1, %2, %0;" : "+l"(acc[i][1]) : "l"(ap), "l"(wp.y));
            }
        }
        __syncthreads();
    }

#pragma unroll
    for (int i = 0; i < 4; i++) {
        int grow = row0 + ty * 4 + i;
        if (grow < n) {
            float4 o;
            unsigned lo0, hi0, lo1, hi1;
            asm("mov.b64 {%0, %1}, %2;" : "=r"(lo0), "=r"(hi0) : "l"(acc[i][0]));
            asm("mov.b64 {%0, %1}, %2;" : "=r"(lo1), "=r"(hi1) : "l"(acc[i][1]));
            o.x = __uint_as_float(lo0);
            o.y = __uint_as_float(hi0);
            o.z = __uint_as_float(lo1);
            o.w = __uint_as_float(hi1);
            *(float4*)(g_h + (size_t)grow * 128 + tx * 4) = o;
        }
    }
}

// ---------------- aggregate: warp per dst node, register accumulation ----------

__global__ __launch_bounds__(256) void agg_kernel(
    const float* __restrict__ bias, float* __restrict__ out_ext,
    int n, int to_gb, int do_relu)
{
    float* out = to_gb ? (float*)g_b : out_ext;
    int warp = (blockIdx.x * blockDim.x + threadIdx.x) >> 5;
    int lane = threadIdx.x & 31;
    if (warp >= n) return;

    float di = g_dinv[warp];
    float sl = di * di;
    float4 hv = *((const float4*)(g_h + (size_t)warp * 128) + lane);
    float4 bv = *((const float4*)bias + lane);
    float4 acc;
    acc.x = hv.x * sl + bv.x;
    acc.y = hv.y * sl + bv.y;
    acc.z = hv.z * sl + bv.z;
    acc.w = hv.w * sl + bv.w;

    int p  = g_rowstart[warp];
    int p1 = g_rowstart[warp + 1];

    for (; p + 3 < p1; p += 4) {
        int   s0 = g_csr_src[p],     s1 = g_csr_src[p + 1];
        int   s2 = g_csr_src[p + 2], s3 = g_csr_src[p + 3];
        float n0 = g_csr_norm[p],     n1 = g_csr_norm[p + 1];
        float n2 = g_csr_norm[p + 2], n3 = g_csr_norm[p + 3];
        float4 v0 = *((const float4*)(g_h + (size_t)s0 * 128) + lane);
        float4 v1 = *((const float4*)(g_h + (size_t)s1 * 128) + lane);
        float4 v2 = *((const float4*)(g_h + (size_t)s2 * 128) + lane);
        float4 v3 = *((const float4*)(g_h + (size_t)s3 * 128) + lane);
        acc.x += n0 * v0.x + n1 * v1.x + n2 * v2.x + n3 * v3.x;
        acc.y += n0 * v0.y + n1 * v1.y + n2 * v2.y + n3 * v3.y;
        acc.z += n0 * v0.z + n1 * v1.z + n2 * v2.z + n3 * v3.z;
        acc.w += n0 * v0.w + n1 * v1.w + n2 * v2.w + n3 * v3.w;
    }
    for (; p < p1; p++) {
        int   sa = g_csr_src[p];
        float na = g_csr_norm[p];
        float4 va = *((const float4*)(g_h + (size_t)sa * 128) + lane);
        acc.x += na * va.x;
        acc.y += na * va.y;
        acc.z += na * va.z;
        acc.w += na * va.w;
    }

    if (do_relu) {
        acc.x = fmaxf(acc.x, 0.f);
        acc.y = fmaxf(acc.y, 0.f);
        acc.z = fmaxf(acc.z, 0.f);
        acc.w = fmaxf(acc.w, 0.f);
    }
    *((float4*)(out + (size_t)warp * 128) + lane) = acc;
}

// ---------------- launch ----------------

extern "C" void kernel_launch(void* const* d_in, const int* in_sizes, int n_in,
                              void* d_out, int out_size) {
    const float* x  = (const float*)d_in[0];
    const void*  ei = d_in[1];
    const float* ew = (const float*)d_in[2];
    const float* W1 = (const float*)d_in[3];
    const float* b1 = (const float*)d_in[4];
    const float* W2 = (const float*)d_in[5];
    const float* b2 = (const float*)d_in[6];
    float*       out = (float*)d_out;

    int n = in_sizes[0] / 128;   // 50000
    int E = in_sizes[2];         // 600000

    const int B = 256;

    probe_zero_kernel<<<(n + B - 1) / B, B>>>((const int*)ei, E, n);
    deg_kernel<<<(E + B - 1) / B, B>>>(ei, ew, E, n);
    scan_dinv_kernel<<<1, 1024>>>(n);
    build_csr_kernel<<<(E + B - 1) / B, B>>>(ei, ew, E, n);

    int gemm_blocks = (n + 63) / 64;
    int agg_blocks = (n * 32 + B - 1) / B;

    // layer 1: h = x@W1 ; g_b = relu(agg(h) + b1)
    gemm128_kernel<<<gemm_blocks, 512>>>(x, W1, n, 0);
    agg_kernel<<<agg_blocks, B>>>(b1, out, n, 1, 1);

    // layer 2: h = g_b@W2 ; out = agg(h) + b2
    gemm128_kernel<<<gemm_blocks, 512>>>(x, W2, n, 1);
    agg_kernel<<<agg_blocks, B>>>(b2, out, n, 0, 0);
}